// round 2
// baseline (speedup 1.0000x reference)
#include <cuda_runtime.h>
#include <cstdint>

// ---------------------------------------------------------------------------
// HexagonalSensor: 16.7M photons -> hex-pixel scatter add (1801 bins)
// Strategy: per-CTA privatized global histograms (REDG, spread over L2 LTS),
// magic-number round-half-even (no F2I/FRND), smem lookup table, tiny reduce.
// ---------------------------------------------------------------------------

#define NCTA 592          // 4 CTAs per SM on 148 SMs
#define TPB  256
#define MAX_PIX 2048      // out_size is 1801; padded

// Scratch: scratch[pix * NCTA + cta]  (pix-major so reduce reads contiguous)
__device__ float g_scratch[MAX_PIX * NCTA];

// -------------------------- zero scratch -----------------------------------
__global__ void zero_kernel(int total4) {
    float4* p = reinterpret_cast<float4*>(g_scratch);
    float4 z = make_float4(0.f, 0.f, 0.f, 0.f);
    for (int i = blockIdx.x * blockDim.x + threadIdx.x; i < total4;
         i += gridDim.x * blockDim.x)
        p[i] = z;
}

// -------------------------- main histogram ---------------------------------
__device__ __forceinline__ void photon_one(
    float x, float y, float v,
    float ca, float sa, float ox, float oy,
    float c1, float c2, float c3,
    int qmin, int rmin, int dim,
    const int* __restrict__ s_lut,
    float* __restrict__ my_col)
{
    // rotate into grid frame
    float xs = x - ox;
    float ys = y - oy;
    float xrot = fmaf(ca, xs, -(sa * ys));
    float yrot = fmaf(sa, xs, ca * ys);

    // cartesian -> axial (constants folded with 1/hex_size)
    float q = fmaf(c1, xrot, c2 * yrot);
    float r = c3 * yrot;
    float s = -q - r;

    // round-half-even via magic add; integer falls out of mantissa bits
    const float MAG = 12582912.0f;           // 1.5 * 2^23
    const int   MAGBITS = 0x4B400000;
    float fq = q + MAG, fr = r + MAG, fs = s + MAG;
    float qr = fq - MAG, rr = fr - MAG, sr = fs - MAG;
    int qi = __float_as_int(fq) - MAGBITS;
    int ri = __float_as_int(fr) - MAGBITS;
    int si = __float_as_int(fs) - MAGBITS;

    // cube-round fixup (faithful to reference _axial_round)
    float qd = fabsf(qr - q), rd = fabsf(rr - r), sd = fabsf(sr - s);
    bool cq = (qd > rd) && (qd > sd);
    bool cr = (rd > qd) && (rd > sd);
    if (cq)      qi = -ri - si;
    else if (cr) ri = -qi - si;

    int q_idx = qi - qmin;
    int r_idx = ri - rmin;
    bool inb = ((unsigned)q_idx < (unsigned)dim) &
               ((unsigned)r_idx < (unsigned)dim);
    int pix = -1;
    if (inb) pix = s_lut[q_idx * dim + r_idx];
    if (pix >= 0) {
        // unused return -> ptxas emits RED.E.ADD.F32 (fire-and-forget to L2)
        atomicAdd(my_col + (size_t)pix * NCTA, v);
    }
}

__global__ __launch_bounds__(TPB)
void hex_kernel(const float* __restrict__ x,
                const float* __restrict__ y,
                const float* __restrict__ vals,
                const int* __restrict__ lut,
                const float* __restrict__ p_hs,
                const float* __restrict__ p_rot,
                const float* __restrict__ p_ox,
                const float* __restrict__ p_oy,
                const int* __restrict__ p_qmin,
                const int* __restrict__ p_rmin,
                int n4, int dim)
{
    __shared__ int s_lut[2448];   // 49*49 = 2401

    for (int i = threadIdx.x; i < dim * dim; i += blockDim.x)
        s_lut[i] = lut[i];

    // runtime scalars (L2-cached, trivially amortized)
    float hs  = *p_hs;
    float rot = *p_rot;
    float ox  = *p_ox;
    float oy  = *p_oy;
    int qmin  = *p_qmin;
    int rmin  = *p_rmin;

    float ca = cosf(-rot), sa = sinf(-rot);
    float inv_hs = 1.0f / hs;
    float c1 = 0.57735026919f * inv_hs;          // (sqrt3/3)/hs
    float c2 = -0.33333333333f * inv_hs;         // -(1/3)/hs
    float c3 = 0.66666666667f * inv_hs;          // (2/3)/hs

    __syncthreads();

    float* my_col = g_scratch + blockIdx.x;      // this CTA's private column

    const float4* x4 = reinterpret_cast<const float4*>(x);
    const float4* y4 = reinterpret_cast<const float4*>(y);
    const float4* v4 = reinterpret_cast<const float4*>(vals);

    int stride = gridDim.x * blockDim.x;
    for (int i = blockIdx.x * blockDim.x + threadIdx.x; i < n4; i += stride) {
        float4 xx = x4[i];
        float4 yy = y4[i];
        float4 vv = v4[i];
        photon_one(xx.x, yy.x, vv.x, ca, sa, ox, oy, c1, c2, c3,
                   qmin, rmin, dim, s_lut, my_col);
        photon_one(xx.y, yy.y, vv.y, ca, sa, ox, oy, c1, c2, c3,
                   qmin, rmin, dim, s_lut, my_col);
        photon_one(xx.z, yy.z, vv.z, ca, sa, ox, oy, c1, c2, c3,
                   qmin, rmin, dim, s_lut, my_col);
        photon_one(xx.w, yy.w, vv.w, ca, sa, ox, oy, c1, c2, c3,
                   qmin, rmin, dim, s_lut, my_col);
    }
}

// -------------------------- final reduce -----------------------------------
__global__ void reduce_kernel(float* __restrict__ out, int npix) {
    int p = blockIdx.x * blockDim.x + threadIdx.x;
    if (p >= npix) return;
    const float4* row = reinterpret_cast<const float4*>(g_scratch + (size_t)p * NCTA);
    float s0 = 0.f, s1 = 0.f, s2 = 0.f, s3 = 0.f;
    #pragma unroll 4
    for (int c = 0; c < NCTA / 4; c++) {
        float4 t = row[c];
        s0 += t.x; s1 += t.y; s2 += t.z; s3 += t.w;
    }
    out[p] = (s0 + s1) + (s2 + s3);
}

// -------------------------- launch -----------------------------------------
extern "C" void kernel_launch(void* const* d_in, const int* in_sizes, int n_in,
                              void* d_out, int out_size)
{
    const float* x    = (const float*)d_in[0];
    const float* y    = (const float*)d_in[1];
    const float* vals = (const float*)d_in[2];
    const int*   lut  = (const int*)  d_in[3];
    const float* hs   = (const float*)d_in[4];
    const float* rot  = (const float*)d_in[5];
    const float* ox   = (const float*)d_in[6];
    const float* oy   = (const float*)d_in[7];
    const int*   qmin = (const int*)  d_in[8];
    const int*   rmin = (const int*)  d_in[9];

    int n = in_sizes[0];
    int lutsize = in_sizes[3];
    int dim = 1;
    while (dim * dim < lutsize) dim++;   // 49 for this problem

    int npix = out_size;                 // 1801
    if (npix > MAX_PIX) npix = MAX_PIX;

    int total4 = (npix * NCTA) / 4;
    zero_kernel<<<256, 256>>>(total4);
    hex_kernel<<<NCTA, TPB>>>(x, y, vals, lut, hs, rot, ox, oy,
                              qmin, rmin, n / 4, dim);
    reduce_kernel<<<(npix + 127) / 128, 128>>>((float*)d_out, npix);
}